// round 2
// baseline (speedup 1.0000x reference)
#include <cuda_runtime.h>
#include <cstdint>

// ---------------------------------------------------------------------------
// SparseResUQueryNet: history sparse conv (1->32) + time max-pool + query
// sparse conv (32->32) evaluated per point.
//
// Keys pack into 28 bits: ((t*256+x)*256+y)*256+z  (t<16, coords in [1,250]).
// Neighbor offsets dx,dy,dz in {-1,0,1} never carry across bytes.
//
// R2 design: exact occupancy BITMAPS answer the (mostly-miss) neighbor
// membership question; hash tables are only probed on true hits.
// ---------------------------------------------------------------------------

#define H1_LOG 22
#define H2_LOG 21
#define H1_SIZE (1u << H1_LOG)
#define H2_SIZE (1u << H2_LOG)
#define H1_MASK (H1_SIZE - 1u)
#define H2_MASK (H2_SIZE - 1u)
#define EMPTY_KEY 0xFFFFFFFFu
#define FULL_MASK 0xFFFFFFFFu
#define BM1_WORDS (1u << 23)   // 2^28 bits = 32 MB  (t,x,y,z)
#define BM2_WORDS (1u << 20)   // 2^25 bits = 4 MB   (b,x,y,z)
#define CONT_BM_WORDS (H2_SIZE / 32)
#define CONT_CAP 65536

// Static scratch (no cudaMalloc allowed).
__device__ unsigned g_h1_keys[H1_SIZE];                // 16 MB
__device__ int      g_h1_vals[H1_SIZE];                // 16 MB (not reset)
__device__ unsigned g_h2_keys[H2_SIZE];                // 8 MB
__device__ unsigned g_bm1[BM1_WORDS];                  // 32 MB
__device__ unsigned g_bm2[BM2_WORDS];                  // 4 MB
__device__ unsigned g_cont_bm[CONT_BM_WORDS];          // 256 KB
__device__ int      g_cont_list[CONT_CAP];
__device__ int      g_cont_cnt;
__device__ unsigned g_pooled[(size_t)H2_SIZE * 32];    // 256 MB (row = slot)

// delta[d] = (dx<<16)+(dy<<8)+dz for d = (dx+1)*9+(dy+1)*3+(dz+1)
__constant__ unsigned c_delta[27] = {
    0xFFFEFEFFu, 0xFFFEFF00u, 0xFFFEFF01u,
    0xFFFEFFFFu, 0xFFFF0000u, 0xFFFF0001u,
    0xFFFF00FFu, 0xFFFF0100u, 0xFFFF0101u,
    0xFFFFFEFFu, 0xFFFFFF00u, 0xFFFFFF01u,
    0xFFFFFFFFu, 0x00000000u, 0x00000001u,
    0x000000FFu, 0x00000100u, 0x00000101u,
    0x0000FEFFu, 0x0000FF00u, 0x0000FF01u,
    0x0000FFFFu, 0x00010000u, 0x00010001u,
    0x000100FFu, 0x00010100u, 0x00010101u
};

__device__ __forceinline__ unsigned hash1(unsigned k) {
    return (k * 2654435761u) >> (32 - H1_LOG);
}
__device__ __forceinline__ unsigned hash2(unsigned k) {
    return (k * 2654435761u) >> (32 - H2_LOG);
}
// Order-preserving float<->uint map (atomicMax pooling on contested rows).
__device__ __forceinline__ unsigned encf(float f) {
    unsigned b = __float_as_uint(f);
    return b ^ (unsigned)(((int)b >> 31) | 0x80000000);
}
__device__ __forceinline__ float decf(unsigned u) {
    unsigned x = ((int)u < 0) ? (u ^ 0x80000000u) : ~u;
    return __uint_as_float(x);
}
__device__ __forceinline__ bool bit_test(const unsigned* bm, unsigned idx) {
    return (bm[idx >> 5] >> (idx & 31)) & 1u;
}

// ---------------------------------------------------------------------------
// K0: reset (uint4 vectorized). pooled is NOT reset: uncontested rows are
// fully overwritten in K2; contested rows are zeroed in K1.
// ---------------------------------------------------------------------------
__global__ void k_reset() {
    unsigned i = blockIdx.x * blockDim.x + threadIdx.x;
    unsigned stride = gridDim.x * blockDim.x;
    const uint4 e4 = make_uint4(EMPTY_KEY, EMPTY_KEY, EMPTY_KEY, EMPTY_KEY);
    const uint4 z4 = make_uint4(0u, 0u, 0u, 0u);
    uint4* h1 = (uint4*)g_h1_keys;
    uint4* h2 = (uint4*)g_h2_keys;
    uint4* b1 = (uint4*)g_bm1;
    uint4* b2 = (uint4*)g_bm2;
    uint4* cb = (uint4*)g_cont_bm;
    for (unsigned s = i; s < H1_SIZE / 4; s += stride) h1[s] = e4;
    for (unsigned s = i; s < H2_SIZE / 4; s += stride) h2[s] = e4;
    for (unsigned s = i; s < BM1_WORDS / 4; s += stride) b1[s] = z4;
    for (unsigned s = i; s < BM2_WORDS / 4; s += stride) b2[s] = z4;
    for (unsigned s = i; s < CONT_BM_WORDS / 4; s += stride) cb[s] = z4;
    if (i == 0) g_cont_cnt = 0;
}

// ---------------------------------------------------------------------------
// K1: set bitmaps; insert history keys into H1 (value = voxel index) and pool
// keys into H2 (row = slot). A thread that finds its pool key already present
// marks the slot contested (once), records it, and zeroes the pooled row.
// ---------------------------------------------------------------------------
__global__ void k_insert(const int4* __restrict__ hcoord,
                         const int* __restrict__ hbatch, int n) {
    int i = blockIdx.x * blockDim.x + threadIdx.x;
    if (i >= n) return;
    int4 c = hcoord[i];  // t, x, y, z
    unsigned key = ((unsigned)c.x << 24) | ((unsigned)c.y << 16) |
                   ((unsigned)c.z << 8) | (unsigned)c.w;
    atomicOr(&g_bm1[key >> 5], 1u << (key & 31));
    unsigned s = hash1(key);
    while (true) {  // history keys are unique (np.unique dedup upstream)
        unsigned old = atomicCAS(&g_h1_keys[s], EMPTY_KEY, key);
        if (old == EMPTY_KEY) { g_h1_vals[s] = i; break; }
        s = (s + 1) & H1_MASK;
    }
    unsigned pk = ((unsigned)hbatch[i] << 24) | ((unsigned)c.y << 16) |
                  ((unsigned)c.z << 8) | (unsigned)c.w;
    atomicOr(&g_bm2[pk >> 5], 1u << (pk & 31));
    s = hash2(pk);
    while (true) {
        unsigned old = atomicCAS(&g_h2_keys[s], EMPTY_KEY, pk);
        if (old == EMPTY_KEY) break;
        if (old == pk) {  // duplicate (b,x,y,z): contested slot
            unsigned prev = atomicOr(&g_cont_bm[s >> 5], 1u << (s & 31));
            if (!(prev & (1u << (s & 31)))) {
                int idx = atomicAdd(&g_cont_cnt, 1);
                if (idx < CONT_CAP) g_cont_list[idx] = (int)s;
            }
            unsigned* row = &g_pooled[(size_t)s * 32];
#pragma unroll
            for (int q = 0; q < 32; q++) row[q] = 0u;  // encoded minimum
            break;
        }
        s = (s + 1) & H2_MASK;
    }
}

// ---------------------------------------------------------------------------
// K2: one warp per history voxel. bb[i][lane] = sum_d f_d * Wbb[d][lane];
// membership via bitmap (lane 13 = self, feature known directly), hash probe
// only on bitmap hits (~0.07 per voxel). Then max-pool into the pool row:
// plain FLOAT store if single-writer, atomicMax(encoded) if contested.
// ---------------------------------------------------------------------------
__global__ void k_bb_pool(const float* __restrict__ hfeat,
                          const float* __restrict__ Wbb,
                          const int4* __restrict__ hcoord,
                          const int* __restrict__ hbatch, int n) {
    int w = (int)((blockIdx.x * blockDim.x + threadIdx.x) >> 5);
    int lane = threadIdx.x & 31;
    if (w >= n) return;
    int4 c = hcoord[w];
    unsigned key = ((unsigned)c.x << 24) | ((unsigned)c.y << 16) |
                   ((unsigned)c.z << 8) | (unsigned)c.w;
    float f = 0.0f;
    bool valid = false;
    if (lane == 13) {
        f = hfeat[w];
        valid = true;
    } else if (lane < 27) {
        unsigned nk = key + c_delta[lane];
        if (bit_test(g_bm1, nk)) {
            unsigned s = hash1(nk);
            while (true) {
                unsigned k2 = g_h1_keys[s];
                if (k2 == nk) { f = hfeat[g_h1_vals[s]]; valid = true; break; }
                if (k2 == EMPTY_KEY) break;
                s = (s + 1) & H1_MASK;
            }
        }
    }
    unsigned m = __ballot_sync(FULL_MASK, valid);
    float acc = 0.0f;
    while (m) {  // ascending d == reference accumulation order
        int d = __ffs(m) - 1;
        m &= m - 1;
        float fd = __shfl_sync(FULL_MASK, f, d);
        acc = fmaf(fd, Wbb[d * 32 + lane], acc);
    }
    unsigned pk = ((unsigned)hbatch[w] << 24) | ((unsigned)c.y << 16) |
                  ((unsigned)c.z << 8) | (unsigned)c.w;
    unsigned s = hash2(pk);
    while (g_h2_keys[s] != pk) s = (s + 1) & H2_MASK;  // always present
    unsigned* addr = &g_pooled[(size_t)s * 32 + lane];
    if (bit_test(g_cont_bm, s)) atomicMax(addr, encf(acc));
    else *addr = __float_as_uint(acc);  // plain float, single writer
}

// ---------------------------------------------------------------------------
// K2b: decode contested rows in place (encoded uint -> plain float).
// ---------------------------------------------------------------------------
__global__ void k_fix() {
    int lane = threadIdx.x & 31;
    int wstride = (int)((gridDim.x * blockDim.x) >> 5);
    int cnt = g_cont_cnt;
    if (cnt > CONT_CAP) cnt = CONT_CAP;
    for (int w = (int)((blockIdx.x * blockDim.x + threadIdx.x) >> 5);
         w < cnt; w += wstride) {
        unsigned* row = &g_pooled[(size_t)g_cont_list[w] * 32];
        row[lane] = __float_as_uint(decf(row[lane]));
    }
}

// ---------------------------------------------------------------------------
// K3: one warp per query point. Lanes 0..26 bitmap-test the 27 neighbors
// (~2% hit rate); hash probe only on hits. For each valid delta: broadcast-
// load the pooled float row, accumulate lane channel with 32 FFMAs against
// W_conv[d]. Write [pt0..3 | 32 features].
// ---------------------------------------------------------------------------
__global__ void k_query(const float* __restrict__ points,
                        const float* __restrict__ Wc,
                        const int4* __restrict__ qcoord,
                        float* __restrict__ out, int npts) {
    int p = (int)((blockIdx.x * blockDim.x + threadIdx.x) >> 5);
    int lane = threadIdx.x & 31;
    if (p >= npts) return;
    int4 c = qcoord[p];  // b, x, y, z
    unsigned key = ((unsigned)c.x << 24) | ((unsigned)c.y << 16) |
                   ((unsigned)c.z << 8) | (unsigned)c.w;
    int r = -1;
    if (lane < 27) {
        unsigned nk = key + c_delta[lane];
        if (bit_test(g_bm2, nk)) {
            unsigned s = hash2(nk);
            while (g_h2_keys[s] != nk) s = (s + 1) & H2_MASK;  // exact bitmap
            r = (int)s;
        }
    }
    unsigned m = __ballot_sync(FULL_MASK, r >= 0);
    float acc = 0.0f;
    while (m) {
        int d = __ffs(m) - 1;
        m &= m - 1;
        int rs = __shfl_sync(FULL_MASK, r, d);
        const float4* prow = (const float4*)&g_pooled[(size_t)rs * 32];
        float pv[32];
#pragma unroll
        for (int q = 0; q < 8; q++) {
            float4 v = prow[q];  // uniform address -> broadcast
            pv[q * 4 + 0] = v.x;
            pv[q * 4 + 1] = v.y;
            pv[q * 4 + 2] = v.z;
            pv[q * 4 + 3] = v.w;
        }
        const float* wb = Wc + d * 1024 + lane;
#pragma unroll
        for (int k = 0; k < 32; k++) acc = fmaf(pv[k], wb[k * 32], acc);
    }
    float* o = out + (size_t)p * 36;
    o[4 + lane] = acc;
    if (lane < 4) o[lane] = points[(size_t)p * 5 + lane];
}

// ---------------------------------------------------------------------------
extern "C" void kernel_launch(void* const* d_in, const int* in_sizes, int n_in,
                              void* d_out, int out_size) {
    const float* hfeat  = (const float*)d_in[0];
    const float* points = (const float*)d_in[1];
    const float* Wbb    = (const float*)d_in[2];
    const float* Wc     = (const float*)d_in[3];
    const int4*  hcoord = (const int4*)d_in[4];
    const int*   hbatch = (const int*)d_in[5];
    const int4*  qcoord = (const int4*)d_in[6];
    float* out = (float*)d_out;

    int n    = in_sizes[5];      // history voxel count
    int npts = in_sizes[6] / 4;  // query point count

    const int TB = 256;
    k_reset<<<4096, TB>>>();
    k_insert<<<(n + TB - 1) / TB, TB>>>(hcoord, hbatch, n);
    {
        long long tw = (long long)n * 32;
        int blocks = (int)((tw + TB - 1) / TB);
        k_bb_pool<<<blocks, TB>>>(hfeat, Wbb, hcoord, hbatch, n);
    }
    k_fix<<<512, TB>>>();
    {
        long long tw = (long long)npts * 32;
        int blocks = (int)((tw + TB - 1) / TB);
        k_query<<<blocks, TB>>>(points, Wc, qcoord, out, npts);
    }
}